// round 7
// baseline (speedup 1.0000x reference)
#include <cuda_runtime.h>
#include <cstdint>

// HOG fused kernel R7: persistent one-wave grid (740 = 148 SM x 5 blocks),
// stripe loop with fused fold+rezero; R5 compute body (float2 tile, float-pipe
// classification, paired overlapped histogram RMW).
// x: (64,1,512,512) f32. out: (64, 9*64*64) f32.
// Stripe = (image n, cell-row cy): 8 rows x 512 cols; 256 thr: cell=t/4, sub=t%4.

#define TS2 646   // tile row stride; col c -> 10*(c>>3)+(c&7)+4, halos at idx 1 / 644

__device__ __forceinline__ uint32_t smem_u32(const void* p)
{
    uint32_t a;
    asm("{ .reg .u64 t; cvta.to.shared.u64 t, %1; cvt.u32.u64 %0, t; }"
        : "=r"(a) : "l"(p));
    return a;
}

__device__ __forceinline__ float setge(float a, float b)
{
    float r;
    asm("set.ge.f32.f32 %0, %1, %2;" : "=f"(r) : "f"(a), "f"(b));
    return r;
}

__device__ __forceinline__ uint32_t hog_class(float gx, float gy, uint32_t hb, float& mag)
{
    float d2 = fmaf(gx, gx, gy * gy);
    asm("sqrt.approx.f32 %0, %1;" : "=f"(mag) : "f"(d2));

    float u = fabsf(gx), v = fabsf(gy);
    float fa = (setge(u, 0.36397023f * v) + setge(u, 0.83909963f * v))
             + (setge(u, 1.73205081f * v) + setge(u, 5.67128182f * v));  // 0..4

    uint32_t bx = __float_as_uint(gx), by = __float_as_uint(gy);
    uint32_t xo = bx ^ by;
    float negfa = __uint_as_float(__float_as_uint(fa) ^ (xo & 0x80000000u));
    float cf = ((int)bx < 0) ? (((int)xo < 0) ? 8.0f : 0.0f)
                             : (((int)xo < 0) ? 17.0f : 9.0f);
    float m = (cf + negfa) + 12582912.0f;        // 0x4B400000 + fl9 (exact)
    return hb + (__float_as_uint(m) << 10);
}

__device__ __forceinline__ void hog_pair(uint32_t a0, float m0, uint32_t a1, float m1)
{
    float msum = m0 + m1;
    asm volatile(
        "{\n\t"
        ".reg .pred p;\n\t"
        ".reg .f32 t0, t1, v0;\n\t"
        "setp.ne.u32 p, %0, %1;\n\t"
        "selp.f32 v0, %2, %3, p;\n\t"
        "ld.shared.f32 t0, [%0];\n\t"
        "@p ld.shared.f32 t1, [%1];\n\t"
        "add.f32 t0, t0, v0;\n\t"
        "@p add.f32 t1, t1, %4;\n\t"
        "st.shared.f32 [%0], t0;\n\t"
        "@p st.shared.f32 [%1], t1;\n\t"
        "}"
        :: "r"(a0), "r"(a1), "f"(m0), "f"(msum), "f"(m1));
}

__device__ __forceinline__ void emit(uint32_t hb, float gx0, float gy0, float gx1, float gy1)
{
    float m0, m1;
    uint32_t q0 = hog_class(gx0, gy0, hb, m0);
    uint32_t q1 = hog_class(gx1, gy1, hb, m1);
    hog_pair(q0, m0, q1, m1);
}

__global__ __launch_bounds__(256, 5)
void hog_kernel(const float* __restrict__ x, float* __restrict__ out)
{
    __shared__ __align__(16) float tile[10 * TS2];
    __shared__ float hist[18 * 256];

    const int tid = threadIdx.x;

    // hoisted per-thread constants
    const int cell = tid >> 2;
    const int sub  = tid & 3;
    const float* pw = &tile[(2 * sub + 0) * TS2 + 10 * cell];
    const float* pa = &tile[(2 * sub + 1) * TS2 + 10 * cell];
    const float* pb = &tile[(2 * sub + 2) * TS2 + 10 * cell];
    const float* pc = &tile[(2 * sub + 3) * TS2 + 10 * cell];
    const uint32_t hb = smem_u32(&hist[tid]);

    // zero own histogram column once; re-zeroed in the fold each stripe
#pragma unroll
    for (int b = 0; b < 18; ++b) hist[b * 256 + tid] = 0.0f;

    for (int s = blockIdx.x; s < 4096; s += 740) {
        const int n  = s >> 6;
        const int cy = s & 63;
        const float* img  = x + (size_t)n * (512 * 512);
        const int    row0 = cy * 8 - 1;

        __syncthreads();   // tile WAR: prior stripe's readers done

        // ---- load 10 rows into padded tile ----
#pragma unroll
        for (int i = 0; i < 5; ++i) {
            int idx = tid + i * 256;
            int r   = idx >> 7;
            int k   = idx & 127;
            int gr  = row0 + r;
            float4 v = make_float4(0.f, 0.f, 0.f, 0.f);
            if ((unsigned)gr < 512u)
                v = *reinterpret_cast<const float4*>(img + (size_t)gr * 512 + k * 4);
            float* d = &tile[r * TS2 + 5 * k + 4 - (k & 1)];
            *reinterpret_cast<float2*>(d)     = make_float2(v.x, v.y);
            *reinterpret_cast<float2*>(d + 2) = make_float2(v.z, v.w);
        }
        if (tid < 10) { tile[tid * TS2 + 1] = 0.f; tile[tid * TS2 + 644] = 0.f; }
        __syncthreads();

        // ---- mainloop: 2 cols per step ----
        float lw = pw[1], la = pa[1], lb = pb[1], lc = pc[1];
        float2 wp = *reinterpret_cast<const float2*>(pw + 4);
        float2 ap = *reinterpret_cast<const float2*>(pa + 4);
        float2 bp = *reinterpret_cast<const float2*>(pb + 4);
        float2 cp = *reinterpret_cast<const float2*>(pc + 4);

        float Am1 = lw + 2.f * la + lb;
        float Bm1 = la + 2.f * lb + lc;
        float A0 = wp.x + 2.f * ap.x + bp.x, A1 = wp.y + 2.f * ap.y + bp.y;
        float B0 = ap.x + 2.f * bp.x + cp.x, B1 = ap.y + 2.f * bp.y + cp.y;

        emit(hb,
             Am1 - A1, (lw + 2.f * wp.x + wp.y) - (lb + 2.f * bp.x + bp.y),
             Bm1 - B1, (la + 2.f * ap.x + ap.y) - (lc + 2.f * cp.x + cp.y));

        float w0 = wp.x, w1 = wp.y, a0 = ap.x, a1 = ap.y;
        float b0 = bp.x, b1 = bp.y, c0 = cp.x, c1 = cp.y;

#pragma unroll
        for (int k = 1; k < 4; ++k) {
            float2 wn = *reinterpret_cast<const float2*>(pw + 4 + 2 * k);
            float2 an = *reinterpret_cast<const float2*>(pa + 4 + 2 * k);
            float2 bn = *reinterpret_cast<const float2*>(pb + 4 + 2 * k);
            float2 cn = *reinterpret_cast<const float2*>(pc + 4 + 2 * k);
            float A2 = wn.x + 2.f * an.x + bn.x, A3 = wn.y + 2.f * an.y + bn.y;
            float B2 = an.x + 2.f * bn.x + cn.x, B3 = an.y + 2.f * bn.y + cn.y;

            emit(hb,
                 A0 - A2, (w0 + 2.f * w1 + wn.x) - (b0 + 2.f * b1 + bn.x),
                 B0 - B2, (a0 + 2.f * a1 + an.x) - (c0 + 2.f * c1 + cn.x));
            emit(hb,
                 A1 - A3, (w1 + 2.f * wn.x + wn.y) - (b1 + 2.f * bn.x + bn.y),
                 B1 - B3, (a1 + 2.f * an.x + an.y) - (c1 + 2.f * cn.x + cn.y));

            w0 = wn.x; w1 = wn.y; a0 = an.x; a1 = an.y;
            b0 = bn.x; b1 = bn.y; c0 = cn.x; c1 = cn.y;
            A0 = A2; A1 = A3; B0 = B2; B1 = B3;
        }

        {
            float rw = pw[14], ra = pa[14], rb = pb[14], rc = pc[14];
            float A8 = rw + 2.f * ra + rb;
            float B8 = ra + 2.f * rb + rc;
            emit(hb,
                 A0 - A8, (w0 + 2.f * w1 + rw) - (b0 + 2.f * b1 + rb),
                 B0 - B8, (a0 + 2.f * a1 + ra) - (c0 + 2.f * c1 + rc));
        }

        asm volatile("" ::: "memory");   // order fold reads after asm RMWs

        // ---- fold own column -> 9 bins, re-zero for next stripe ----
        float P[18];
#pragma unroll
        for (int q = 0; q < 18; ++q) {
            P[q] = hist[q * 256 + tid];
            hist[q * 256 + tid] = 0.0f;
        }
        float bin[9];
        bin[0] = (P[0] + P[8]) + (P[9] + P[17]);
#pragma unroll
        for (int b = 1; b < 9; ++b) bin[b] = (P[b - 1] + P[b]) + (P[b + 8] + P[b + 9]);

#pragma unroll
        for (int b = 0; b < 9; ++b) {
            bin[b] += __shfl_xor_sync(0xffffffffu, bin[b], 1);
            bin[b] += __shfl_xor_sync(0xffffffffu, bin[b], 2);
        }

        if (sub == 0) {
            float* o = out + (size_t)n * 36864 + cy * 64 + cell;
#pragma unroll
            for (int b = 0; b < 9; ++b)
                o[(size_t)b * 4096] = bin[b] * 0.015625f;   // 1/64
        }
    }
}

extern "C" void kernel_launch(void* const* d_in, const int* in_sizes, int n_in,
                              void* d_out, int out_size)
{
    const float* x = (const float*)d_in[0];
    float* out = (float*)d_out;
    (void)in_sizes; (void)n_in; (void)out_size;
    hog_kernel<<<740, 256>>>(x, out);
}

// round 8
// speedup vs baseline: 1.0460x; 1.0460x over previous
#include <cuda_runtime.h>
#include <cstdint>

// HOG fused kernel R8: no smem tile — direct GMEM loads + warp-shuffle halos.
// x: (64,1,512,512) f32. out: (64, 9*64*64) f32.
// Block = (image n, cell-row cy) stripe; 256 thr: cell = t/4 (8 cols), sub = t%4 (2 px rows).
// Thread loads its 4 source rows (2sub-1..2sub+2) x 8 cols via LDG.128;
// halo cols 8c-1 / 8c+8 come from lanes +-4 (same sub, neighbor cell) via shfl.

__device__ __forceinline__ uint32_t smem_u32(const void* p)
{
    uint32_t a;
    asm("{ .reg .u64 t; cvta.to.shared.u64 t, %1; cvt.u32.u64 %0, t; }"
        : "=r"(a) : "l"(p));
    return a;
}

__device__ __forceinline__ float setge(float a, float b)
{
    float r;
    asm("set.ge.f32.f32 %0, %1, %2;" : "=f"(r) : "f"(a), "f"(b));
    return r;
}

__device__ __forceinline__ uint32_t hog_class(float gx, float gy, uint32_t hb, float& mag)
{
    float d2 = fmaf(gx, gx, gy * gy);
    asm("sqrt.approx.f32 %0, %1;" : "=f"(mag) : "f"(d2));

    float u = fabsf(gx), v = fabsf(gy);
    float fa = (setge(u, 0.36397023f * v) + setge(u, 0.83909963f * v))
             + (setge(u, 1.73205081f * v) + setge(u, 5.67128182f * v));  // 0..4

    uint32_t bx = __float_as_uint(gx), by = __float_as_uint(gy);
    uint32_t xo = bx ^ by;
    float negfa = __uint_as_float(__float_as_uint(fa) ^ (xo & 0x80000000u));
    float cf = ((int)bx < 0) ? (((int)xo < 0) ? 8.0f : 0.0f)
                             : (((int)xo < 0) ? 17.0f : 9.0f);
    float m = (cf + negfa) + 12582912.0f;        // 0x4B400000 + fl9 (exact)
    return hb + (__float_as_uint(m) << 10);
}

__device__ __forceinline__ void hog_pair(uint32_t a0, float m0, uint32_t a1, float m1)
{
    float msum = m0 + m1;
    asm volatile(
        "{\n\t"
        ".reg .pred p;\n\t"
        ".reg .f32 t0, t1, v0;\n\t"
        "setp.ne.u32 p, %0, %1;\n\t"
        "selp.f32 v0, %2, %3, p;\n\t"
        "ld.shared.f32 t0, [%0];\n\t"
        "@p ld.shared.f32 t1, [%1];\n\t"
        "add.f32 t0, t0, v0;\n\t"
        "@p add.f32 t1, t1, %4;\n\t"
        "st.shared.f32 [%0], t0;\n\t"
        "@p st.shared.f32 [%1], t1;\n\t"
        "}"
        :: "r"(a0), "r"(a1), "f"(m0), "f"(msum), "f"(m1));
}

__device__ __forceinline__ void emit(uint32_t hb, float gx0, float gy0, float gx1, float gy1)
{
    float m0, m1;
    uint32_t q0 = hog_class(gx0, gy0, hb, m0);
    uint32_t q1 = hog_class(gx1, gy1, hb, m1);
    hog_pair(q0, m0, q1, m1);
}

__global__ __launch_bounds__(256, 4)
void hog_kernel(const float* __restrict__ x, float* __restrict__ out)
{
    __shared__ float hist[18 * 256];

    const int tid  = threadIdx.x;
    const int n    = blockIdx.x >> 6;
    const int cy   = blockIdx.x & 63;
    const int cell = tid >> 2;
    const int sub  = tid & 3;
    const int lane = tid & 31;
    const uint32_t hb = smem_u32(&hist[tid]);

#pragma unroll
    for (int b = 0; b < 18; ++b) hist[b * 256 + tid] = 0.0f;
    asm volatile("" ::: "memory");

    // ---- load 4 rows x 8 cols (register tile), all LDG upfront for MLP ----
    const float* img = x + (size_t)n * (512 * 512);
    const int c0 = cell * 8;
    const int rb = cy * 8 + 2 * sub - 1;

    float4 L[4], R[4];
#pragma unroll
    for (int i = 0; i < 4; ++i) {
        int r = rb + i;
        if ((unsigned)r < 512u) {
            const float* rp = img + (size_t)r * 512 + c0;
            L[i] = *reinterpret_cast<const float4*>(rp);
            R[i] = *reinterpret_cast<const float4*>(rp + 4);
        } else {
            L[i] = make_float4(0.f, 0.f, 0.f, 0.f);
            R[i] = make_float4(0.f, 0.f, 0.f, 0.f);
        }
    }

    // ---- halo columns via shuffle (lane-4 / lane+4 = neighbor cell, same sub) ----
    float lf[4], rg[4];
#pragma unroll
    for (int i = 0; i < 4; ++i) {
        lf[i] = __shfl_up_sync(0xffffffffu, R[i].w, 4);   // col 8c-1
        rg[i] = __shfl_down_sync(0xffffffffu, L[i].x, 4); // col 8c+8
    }
    if (lane < 4) {           // warp's first cell: fetch left halo (or image edge 0)
#pragma unroll
        for (int i = 0; i < 4; ++i) {
            int r = rb + i;
            lf[i] = ((unsigned)r < 512u && c0 > 0) ? img[(size_t)r * 512 + c0 - 1] : 0.f;
        }
    }
    if (lane >= 28) {         // warp's last cell: fetch right halo (or image edge 0)
#pragma unroll
        for (int i = 0; i < 4; ++i) {
            int r = rb + i;
            rg[i] = ((unsigned)r < 512u && c0 + 8 < 512) ? img[(size_t)r * 512 + c0 + 8] : 0.f;
        }
    }

    // ---- assemble 10-wide row arrays (pure registers after unroll) ----
    float r0[10], r1[10], r2[10], r3[10];
    {
        float* rows[4] = {r0, r1, r2, r3};
#pragma unroll
        for (int i = 0; i < 4; ++i) {
            rows[i][0] = lf[i];
            rows[i][1] = L[i].x; rows[i][2] = L[i].y; rows[i][3] = L[i].z; rows[i][4] = L[i].w;
            rows[i][5] = R[i].x; rows[i][6] = R[i].y; rows[i][7] = R[i].z; rows[i][8] = R[i].w;
            rows[i][9] = rg[i];
        }
    }

    // ---- vertical [1,2,1] column sums, then per-column gradients ----
    float T[10], B[10];
#pragma unroll
    for (int j = 0; j < 10; ++j) {
        T[j] = r0[j] + 2.f * r1[j] + r2[j];   // top px row (row 2sub)
        B[j] = r1[j] + 2.f * r2[j] + r3[j];   // bottom px row (row 2sub+1)
    }

#pragma unroll
    for (int j = 1; j <= 8; ++j) {
        float gxT = T[j - 1] - T[j + 1];
        float gyT = (r0[j - 1] + 2.f * r0[j] + r0[j + 1])
                  - (r2[j - 1] + 2.f * r2[j] + r2[j + 1]);
        float gxB = B[j - 1] - B[j + 1];
        float gyB = (r1[j - 1] + 2.f * r1[j] + r1[j + 1])
                  - (r3[j - 1] + 2.f * r3[j] + r3[j + 1]);
        emit(hb, gxT, gyT, gxB, gyB);
    }

    asm volatile("" ::: "memory");   // order fold reads after asm RMWs

    // ---- fold own P column -> 9 bins, shuffle-reduce 4 subs, write ----
    float P[18];
#pragma unroll
    for (int s = 0; s < 18; ++s) P[s] = hist[s * 256 + tid];
    float bin[9];
    bin[0] = (P[0] + P[8]) + (P[9] + P[17]);
#pragma unroll
    for (int b = 1; b < 9; ++b) bin[b] = (P[b - 1] + P[b]) + (P[b + 8] + P[b + 9]);

#pragma unroll
    for (int b = 0; b < 9; ++b) {
        bin[b] += __shfl_xor_sync(0xffffffffu, bin[b], 1);
        bin[b] += __shfl_xor_sync(0xffffffffu, bin[b], 2);
    }

    if (sub == 0) {
        float* o = out + (size_t)n * 36864 + cy * 64 + cell;
#pragma unroll
        for (int b = 0; b < 9; ++b)
            o[(size_t)b * 4096] = bin[b] * 0.015625f;   // 1/64
    }
}

extern "C" void kernel_launch(void* const* d_in, const int* in_sizes, int n_in,
                              void* d_out, int out_size)
{
    const float* x = (const float*)d_in[0];
    float* out = (float*)d_out;
    (void)in_sizes; (void)n_in; (void)out_size;
    hog_kernel<<<4096, 256>>>(x, out);
}

// round 9
// speedup vs baseline: 1.2462x; 1.1913x over previous
#include <cuda_runtime.h>
#include <cstdint>

// HOG fused kernel R9: R5 body + 9-slot mod-9 histogram + collapsed classification.
// x: (64,1,512,512) f32. out: (64, 9*64*64) f32.
// Block = (image n, cell-row cy) stripe, 256 threads: cell = t/4, sub = t%4 (2 rows).
// Tile: col c -> 10*(c>>3) + (c&7) + 4 (cell stride 10, conflict-free); halos idx 1/644.
// Histogram: P9[(floor(atan2*9/pi)) mod 9] += mag; bin[b] = P9[b] + P9[(b+8)%9].

#define TS2 646

__device__ __forceinline__ uint32_t smem_u32(const void* p)
{
    uint32_t a;
    asm("{ .reg .u64 t; cvta.to.shared.u64 t, %1; cvt.u32.u64 %0, t; }"
        : "=r"(a) : "l"(p));
    return a;
}

__device__ __forceinline__ float setge(float a, float b)
{
    float r;
    asm("set.ge.f32.f32 %0, %1, %2;" : "=f"(r) : "f"(a), "f"(b));
    return r;
}

// smem byte address of 9-slot histogram bucket for this pixel; mag by ref.
// slot = fl mod 9, where fl = floor(atan2(gx,gy)*9/pi). For all sign quadrants
// this reduces to: slot = |fa - (signs_differ ? 8 : 0)|, fa = #boundaries passed.
__device__ __forceinline__ uint32_t hog_class(float gx, float gy, uint32_t hb, float& mag)
{
    float d2 = fmaf(gx, gx, gy * gy);
    asm("sqrt.approx.f32 %0, %1;" : "=f"(mag) : "f"(d2));

    float u = fabsf(gx), v = fabsf(gy);
    float fa = (setge(u, 0.36397023f * v) + setge(u, 0.83909963f * v))
             + (setge(u, 1.73205081f * v) + setge(u, 5.67128182f * v));  // 0..4

    uint32_t xo = __float_as_uint(gx) ^ __float_as_uint(gy);
    float cf8 = ((int)xo < 0) ? 8.0f : 0.0f;
    float m = fabsf(fa - cf8) + 12582912.0f;     // 0x4B400000 + slot (exact)
    return hb + (__float_as_uint(m) << 10);      // slot * 1024B (magic<<10 == 0 mod 2^32)
}

// two hist RMWs with overlapped LDS chains; merged when same slot.
__device__ __forceinline__ void hog_pair(uint32_t a0, float m0, uint32_t a1, float m1)
{
    float msum = m0 + m1;
    asm volatile(
        "{\n\t"
        ".reg .pred p;\n\t"
        ".reg .f32 t0, t1, v0;\n\t"
        "setp.ne.u32 p, %0, %1;\n\t"
        "selp.f32 v0, %2, %3, p;\n\t"
        "ld.shared.f32 t0, [%0];\n\t"
        "@p ld.shared.f32 t1, [%1];\n\t"
        "add.f32 t0, t0, v0;\n\t"
        "@p add.f32 t1, t1, %4;\n\t"
        "st.shared.f32 [%0], t0;\n\t"
        "@p st.shared.f32 [%1], t1;\n\t"
        "}"
        :: "r"(a0), "r"(a1), "f"(m0), "f"(msum), "f"(m1));
}

__device__ __forceinline__ void emit(uint32_t hb, float gx0, float gy0, float gx1, float gy1)
{
    float m0, m1;
    uint32_t q0 = hog_class(gx0, gy0, hb, m0);
    uint32_t q1 = hog_class(gx1, gy1, hb, m1);
    hog_pair(q0, m0, q1, m1);
}

__global__ __launch_bounds__(256, 5)
void hog_kernel(const float* __restrict__ x, float* __restrict__ out)
{
    __shared__ __align__(16) float tile[10 * TS2];
    __shared__ float hist[9 * 256];

    const int tid = threadIdx.x;
    const int n   = blockIdx.x >> 6;
    const int cy  = blockIdx.x & 63;

#pragma unroll
    for (int b = 0; b < 9; ++b) hist[b * 256 + tid] = 0.0f;

    // ---- load 10 rows into padded tile ----
    const float* img  = x + (size_t)n * (512 * 512);
    const int    row0 = cy * 8 - 1;
#pragma unroll
    for (int i = 0; i < 5; ++i) {
        int idx = tid + i * 256;
        int r   = idx >> 7;
        int k   = idx & 127;
        int gr  = row0 + r;
        float4 v = make_float4(0.f, 0.f, 0.f, 0.f);
        if ((unsigned)gr < 512u)
            v = *reinterpret_cast<const float4*>(img + (size_t)gr * 512 + k * 4);
        float* d = &tile[r * TS2 + 5 * k + 4 - (k & 1)];
        *reinterpret_cast<float2*>(d)     = make_float2(v.x, v.y);
        *reinterpret_cast<float2*>(d + 2) = make_float2(v.z, v.w);
    }
    if (tid < 10) { tile[tid * TS2 + 1] = 0.f; tile[tid * TS2 + 644] = 0.f; }
    __syncthreads();

    // ---- mainloop: thread = cell (8 cols) x 2 rows; 2 cols per step ----
    const int cell = tid >> 2;
    const int sub  = tid & 3;
    const float* pw = &tile[(2 * sub + 0) * TS2 + 10 * cell];
    const float* pa = &tile[(2 * sub + 1) * TS2 + 10 * cell];
    const float* pb = &tile[(2 * sub + 2) * TS2 + 10 * cell];
    const float* pc = &tile[(2 * sub + 3) * TS2 + 10 * cell];
    const uint32_t hb = smem_u32(&hist[tid]);

    float lw = pw[1], la = pa[1], lb = pb[1], lc = pc[1];   // col -1 halo
    float2 wp = *reinterpret_cast<const float2*>(pw + 4);
    float2 ap = *reinterpret_cast<const float2*>(pa + 4);
    float2 bp = *reinterpret_cast<const float2*>(pb + 4);
    float2 cp = *reinterpret_cast<const float2*>(pc + 4);

    float Am1 = lw + 2.f * la + lb;
    float Bm1 = la + 2.f * lb + lc;
    float A0 = wp.x + 2.f * ap.x + bp.x, A1 = wp.y + 2.f * ap.y + bp.y;
    float B0 = ap.x + 2.f * bp.x + cp.x, B1 = ap.y + 2.f * bp.y + cp.y;

    emit(hb,
         Am1 - A1, (lw + 2.f * wp.x + wp.y) - (lb + 2.f * bp.x + bp.y),
         Bm1 - B1, (la + 2.f * ap.x + ap.y) - (lc + 2.f * cp.x + cp.y));

    float w0 = wp.x, w1 = wp.y, a0 = ap.x, a1 = ap.y;
    float b0 = bp.x, b1 = bp.y, c0 = cp.x, c1 = cp.y;

#pragma unroll
    for (int k = 1; k < 4; ++k) {
        float2 wn = *reinterpret_cast<const float2*>(pw + 4 + 2 * k);
        float2 an = *reinterpret_cast<const float2*>(pa + 4 + 2 * k);
        float2 bn = *reinterpret_cast<const float2*>(pb + 4 + 2 * k);
        float2 cn = *reinterpret_cast<const float2*>(pc + 4 + 2 * k);
        float A2 = wn.x + 2.f * an.x + bn.x, A3 = wn.y + 2.f * an.y + bn.y;
        float B2 = an.x + 2.f * bn.x + cn.x, B3 = an.y + 2.f * bn.y + cn.y;

        emit(hb,
             A0 - A2, (w0 + 2.f * w1 + wn.x) - (b0 + 2.f * b1 + bn.x),
             B0 - B2, (a0 + 2.f * a1 + an.x) - (c0 + 2.f * c1 + cn.x));
        emit(hb,
             A1 - A3, (w1 + 2.f * wn.x + wn.y) - (b1 + 2.f * bn.x + bn.y),
             B1 - B3, (a1 + 2.f * an.x + an.y) - (c1 + 2.f * cn.x + cn.y));

        w0 = wn.x; w1 = wn.y; a0 = an.x; a1 = an.y;
        b0 = bn.x; b1 = bn.y; c0 = cn.x; c1 = cn.y;
        A0 = A2; A1 = A3; B0 = B2; B1 = B3;
    }

    // tail: col 7 with right halo col 8 (scalar at offset 14)
    {
        float rw = pw[14], ra = pa[14], rb = pb[14], rc = pc[14];
        float A8 = rw + 2.f * ra + rb;
        float B8 = ra + 2.f * rb + rc;
        emit(hb,
             A0 - A8, (w0 + 2.f * w1 + rw) - (b0 + 2.f * b1 + rb),
             B0 - B8, (a0 + 2.f * a1 + ra) - (c0 + 2.f * c1 + rc));
    }

    asm volatile("" ::: "memory");   // order fold reads after asm RMWs

    // ---- fold: bin[b] = P9[b] + P9[(b+8)%9]; shuffle-reduce 4 subs; write ----
    float P[9];
#pragma unroll
    for (int s = 0; s < 9; ++s) P[s] = hist[s * 256 + tid];
    float bin[9];
#pragma unroll
    for (int b = 0; b < 9; ++b) bin[b] = P[b] + P[(b + 8) % 9];

#pragma unroll
    for (int b = 0; b < 9; ++b) {
        bin[b] += __shfl_xor_sync(0xffffffffu, bin[b], 1);
        bin[b] += __shfl_xor_sync(0xffffffffu, bin[b], 2);
    }

    if (sub == 0) {
        float* o = out + (size_t)n * 36864 + cy * 64 + cell;
#pragma unroll
        for (int b = 0; b < 9; ++b)
            o[(size_t)b * 4096] = bin[b] * 0.015625f;   // 1/64
    }
}

extern "C" void kernel_launch(void* const* d_in, const int* in_sizes, int n_in,
                              void* d_out, int out_size)
{
    const float* x = (const float*)d_in[0];
    float* out = (float*)d_out;
    (void)in_sizes; (void)n_in; (void)out_size;
    hog_kernel<<<4096, 256>>>(x, out);
}